// round 1
// baseline (speedup 1.0000x reference)
#include <cuda_runtime.h>
#include <math.h>
#include <stdint.h>

#define NN 100000
#define NE 800000
#define FD 300

// ---------------- scratch (no allocations allowed) ----------------
__device__ float g_buf0[(size_t)NN * FD];
__device__ float g_buf1[(size_t)NN * FD];
__device__ int   g_csr[NE];
__device__ int   g_rowoff[NN + 1];
__device__ int   g_cnt[NN];
__device__ int   g_cursor[NN];

// ---------------- CSR build ----------------
__global__ void hist_kernel(const int* __restrict__ dst, int n) {
    int i = blockIdx.x * blockDim.x + threadIdx.x;
    if (i < n) atomicAdd(&g_cnt[dst[i]], 1);
}

__global__ void scan_kernel() {
    __shared__ int sh[1024];
    int tid = threadIdx.x;
    int base = 0;
    if (tid == 0) g_rowoff[0] = 0;
    for (int c = 0; c < NN; c += 1024) {
        int i = c + tid;
        int v = (i < NN) ? g_cnt[i] : 0;
        sh[tid] = v;
        __syncthreads();
        #pragma unroll
        for (int off = 1; off < 1024; off <<= 1) {
            int t = (tid >= off) ? sh[tid - off] : 0;
            __syncthreads();
            sh[tid] += t;
            __syncthreads();
        }
        if (i < NN) {
            g_rowoff[i + 1] = base + sh[tid];
            g_cursor[i]     = base + sh[tid] - v;   // exclusive start
        }
        base += sh[1023];
        __syncthreads();
    }
}

__global__ void scatter_kernel(const int* __restrict__ src, const int* __restrict__ dst, int n) {
    int i = blockIdx.x * blockDim.x + threadIdx.x;
    if (i < n) {
        int d = dst[i];
        int pos = atomicAdd(&g_cursor[d], 1);
        g_csr[pos] = src[i];
    }
}

// ---------------- aggregation: out[v] = sum_{e: dst=v} x[src[e]] ----------------
// one block (96 threads, 75 active float4 lanes) per node
__global__ void agg_kernel(const float* __restrict__ x, float* __restrict__ out) {
    int v = blockIdx.x;
    int t = threadIdx.x;
    int beg = g_rowoff[v];
    int end = g_rowoff[v + 1];
    if (t < 75) {
        float4 acc = make_float4(0.f, 0.f, 0.f, 0.f);
        for (int e = beg; e < end; e++) {
            int s = g_csr[e];
            float4 val = ((const float4*)(x + (size_t)s * FD))[t];
            acc.x += val.x; acc.y += val.y; acc.z += val.z; acc.w += val.w;
        }
        ((float4*)(out + (size_t)v * FD))[t] = acc;
    }
}

// ---------------- fp32 tiled GEMM: C[M,300] = A[M,300] * W[300,300]^T ----------------
#define BM 128
#define BN 64
#define BK 20
#define TM 8
#define TN 4
// 256 threads: 16 (n) x 16 (m)
__global__ __launch_bounds__(256) void gemm_nt(const float* __restrict__ A,
                                               const float* __restrict__ W,
                                               float* __restrict__ C, int M) {
    __shared__ float As[BK][BM + 4];
    __shared__ float Ws[BK][BN + 4];
    int tid = threadIdx.x;
    int bm = blockIdx.x * BM;
    int bn = blockIdx.y * BN;
    int tx = tid & 15;       // n
    int ty = tid >> 4;       // m
    float acc[TM][TN];
    #pragma unroll
    for (int i = 0; i < TM; i++)
        #pragma unroll
        for (int j = 0; j < TN; j++) acc[i][j] = 0.f;

    for (int k0 = 0; k0 < FD; k0 += BK) {
        #pragma unroll
        for (int i = 0; i < (BM * BK) / 256; i++) {
            int idx = tid + i * 256;
            int m = idx / BK, k = idx % BK;
            int gm = bm + m;
            As[k][m] = (gm < M) ? A[(size_t)gm * FD + k0 + k] : 0.f;
        }
        #pragma unroll
        for (int i = 0; i < (BN * BK) / 256; i++) {
            int idx = tid + i * 256;
            int n = idx / BK, k = idx % BK;
            int gn = bn + n;
            Ws[k][n] = (gn < FD) ? W[(size_t)gn * FD + k0 + k] : 0.f;
        }
        __syncthreads();
        #pragma unroll
        for (int k = 0; k < BK; k++) {
            float a[TM], w[TN];
            #pragma unroll
            for (int i = 0; i < TM; i++) a[i] = As[k][ty * TM + i];
            #pragma unroll
            for (int j = 0; j < TN; j++) w[j] = Ws[k][tx * TN + j];
            #pragma unroll
            for (int i = 0; i < TM; i++)
                #pragma unroll
                for (int j = 0; j < TN; j++) acc[i][j] += a[i] * w[j];
        }
        __syncthreads();
    }
    #pragma unroll
    for (int i = 0; i < TM; i++) {
        int gm = bm + ty * TM + i;
        if (gm < M) {
            #pragma unroll
            for (int j = 0; j < TN; j++) {
                int gn = bn + tx * TN + j;
                if (gn < FD) C[(size_t)gm * FD + gn] = acc[i][j];
            }
        }
    }
}

// ---------------- bias + softmax over 300 (one block per row, 320 threads) ----------------
__global__ __launch_bounds__(320) void bias_softmax_kernel(const float* __restrict__ h,
                                                           const float* __restrict__ b,
                                                           float* __restrict__ out) {
    int v = blockIdx.x;
    int f = threadIdx.x;
    __shared__ float s_max[10];
    __shared__ float s_sum[10];
    __shared__ float s_m, s_s;

    float x = -1e30f;
    if (f < FD) x = h[(size_t)v * FD + f] + b[f];

    // block max
    float m = x;
    #pragma unroll
    for (int off = 16; off; off >>= 1) m = fmaxf(m, __shfl_xor_sync(0xffffffffu, m, off));
    if ((f & 31) == 0) s_max[f >> 5] = m;
    __syncthreads();
    if (f < 32) {
        float t = (f < 10) ? s_max[f] : -1e30f;
        #pragma unroll
        for (int off = 16; off; off >>= 1) t = fmaxf(t, __shfl_xor_sync(0xffffffffu, t, off));
        if (f == 0) s_m = t;
    }
    __syncthreads();
    float mm = s_m;

    float e = (f < FD) ? __expf(x - mm) : 0.f;
    float s = e;
    #pragma unroll
    for (int off = 16; off; off >>= 1) s += __shfl_xor_sync(0xffffffffu, s, off);
    if ((f & 31) == 0) s_sum[f >> 5] = s;
    __syncthreads();
    if (f < 32) {
        float t = (f < 10) ? s_sum[f] : 0.f;
        #pragma unroll
        for (int off = 16; off; off >>= 1) t += __shfl_xor_sync(0xffffffffu, t, off);
        if (f == 0) s_s = t;
    }
    __syncthreads();
    if (f < FD) out[(size_t)v * FD + f] = e / s_s;
}

// ---------------- bias + relu (elementwise) ----------------
__global__ void bias_relu_kernel(const float* __restrict__ h, const float* __restrict__ b,
                                 float* __restrict__ out, int n) {
    int i = blockIdx.x * blockDim.x + threadIdx.x;
    if (i < n) {
        int f = i % FD;
        out[i] = fmaxf(h[i] + b[f], 0.f);
    }
}

// ---------------- final layer: out = log_softmax(agg @ W4^T + b4), warp per node ----------------
__global__ void final_kernel(const float* __restrict__ agg, const float* __restrict__ W4,
                             const float* __restrict__ b4, float* __restrict__ out) {
    int warp = (blockIdx.x * blockDim.x + threadIdx.x) >> 5;
    int lane = threadIdx.x & 31;
    if (warp >= NN) return;
    const float* a = agg + (size_t)warp * FD;
    float s0 = 0.f, s1 = 0.f, s2 = 0.f;
    for (int k = lane; k < FD; k += 32) {
        float av = a[k];
        s0 += av * W4[k];
        s1 += av * W4[FD + k];
        s2 += av * W4[2 * FD + k];
    }
    #pragma unroll
    for (int off = 16; off; off >>= 1) {
        s0 += __shfl_down_sync(0xffffffffu, s0, off);
        s1 += __shfl_down_sync(0xffffffffu, s1, off);
        s2 += __shfl_down_sync(0xffffffffu, s2, off);
    }
    if (lane == 0) {
        s0 += b4[0]; s1 += b4[1]; s2 += b4[2];
        float m = fmaxf(s0, fmaxf(s1, s2));
        float lse = m + logf(expf(s0 - m) + expf(s1 - m) + expf(s2 - m));
        out[(size_t)warp * 3 + 0] = s0 - lse;
        out[(size_t)warp * 3 + 1] = s1 - lse;
        out[(size_t)warp * 3 + 2] = s2 - lse;
    }
}

// ---------------- launcher ----------------
extern "C" void kernel_launch(void* const* d_in, const int* in_sizes, int n_in,
                              void* d_out, int out_size) {
    const float* features = (const float*)d_in[0];
    const int*   src      = (const int*)d_in[1];
    const int*   dst      = (const int*)d_in[2];
    const float* W1 = (const float*)d_in[3];
    const float* b1 = (const float*)d_in[4];
    const float* W2 = (const float*)d_in[5];
    const float* b2 = (const float*)d_in[6];
    const float* W3 = (const float*)d_in[7];
    const float* b3 = (const float*)d_in[8];
    const float* W4 = (const float*)d_in[9];
    const float* b4 = (const float*)d_in[10];
    float* out = (float*)d_out;

    float *buf0, *buf1;
    int *cnt;
    cudaGetSymbolAddress((void**)&buf0, g_buf0);
    cudaGetSymbolAddress((void**)&buf1, g_buf1);
    cudaGetSymbolAddress((void**)&cnt,  g_cnt);

    const int E = NE;
    int eb = (E + 255) / 256;

    // CSR build (by destination)
    cudaMemsetAsync(cnt, 0, NN * sizeof(int));
    hist_kernel<<<eb, 256>>>(dst, E);
    scan_kernel<<<1, 1024>>>();
    scatter_kernel<<<eb, 256>>>(src, dst, E);

    dim3 ggrid((NN + BM - 1) / BM, (FD + BN - 1) / BN);

    // Layer 1: agg(features)->buf0, gemm->buf1, softmax->buf0
    agg_kernel<<<NN, 96>>>(features, buf0);
    gemm_nt<<<ggrid, 256>>>(buf0, W1, buf1, NN);
    bias_softmax_kernel<<<NN, 320>>>(buf1, b1, buf0);

    // Layer 2: agg(buf0)->buf1, gemm->buf0, softmax->buf1
    agg_kernel<<<NN, 96>>>(buf0, buf1);
    gemm_nt<<<ggrid, 256>>>(buf1, W2, buf0, NN);
    bias_softmax_kernel<<<NN, 320>>>(buf0, b2, buf1);

    // Layer 3: agg(buf1)->buf0, gemm->buf1, relu->buf0
    agg_kernel<<<NN, 96>>>(buf1, buf0);
    gemm_nt<<<ggrid, 256>>>(buf0, W3, buf1, NN);
    {
        int n = NN * FD;
        bias_relu_kernel<<<(n + 255) / 256, 256>>>(buf1, b3, buf0, n);
    }

    // Layer 4: agg(buf0)->buf1, fused small gemm + log_softmax -> out
    agg_kernel<<<NN, 96>>>(buf0, buf1);
    final_kernel<<<(NN * 32 + 255) / 256, 256>>>(buf1, W4, b4, out);
}

// round 3
// speedup vs baseline: 1.4885x; 1.4885x over previous
#include <cuda_runtime.h>
#include <math.h>
#include <stdint.h>

#define NN 100000
#define NE 800000
#define FD 300

// ---------------- scratch (no allocations allowed) ----------------
__device__ float g_buf0[(size_t)NN * FD];
__device__ float g_buf1[(size_t)NN * FD];
__device__ int   g_csr[NE];
__device__ int   g_rowoff[NN + 1];
__device__ int   g_cnt[NN];
__device__ int   g_cursor[NN];
__device__ int   g_bsum[128];
__device__ int   g_boff[128];

// ---------------- CSR build ----------------
__global__ void hist_kernel(const int* __restrict__ dst, int n) {
    int i = blockIdx.x * blockDim.x + threadIdx.x;
    if (i < n) atomicAdd(&g_cnt[dst[i]], 1);
}

// multi-block scan: 98 blocks x 1024
__global__ void scan1_kernel() {
    __shared__ int sh[1024];
    int tid = threadIdx.x;
    int i = blockIdx.x * 1024 + tid;
    int v = (i < NN) ? g_cnt[i] : 0;
    sh[tid] = v;
    __syncthreads();
    #pragma unroll
    for (int off = 1; off < 1024; off <<= 1) {
        int t = (tid >= off) ? sh[tid - off] : 0;
        __syncthreads();
        sh[tid] += t;
        __syncthreads();
    }
    if (i < NN) g_rowoff[i + 1] = sh[tid];   // local inclusive
    if (tid == 1023) g_bsum[blockIdx.x] = sh[1023];
}

__global__ void scan2_kernel() {  // 1 block, 128 threads
    __shared__ int sh[128];
    int tid = threadIdx.x;
    int v = (tid < 98) ? g_bsum[tid] : 0;
    sh[tid] = v;
    __syncthreads();
    #pragma unroll
    for (int off = 1; off < 128; off <<= 1) {
        int t = (tid >= off) ? sh[tid - off] : 0;
        __syncthreads();
        sh[tid] += t;
        __syncthreads();
    }
    g_boff[tid] = sh[tid] - v;  // exclusive
    if (tid == 0) g_rowoff[0] = 0;
}

__global__ void scan3_kernel() {
    int i = blockIdx.x * blockDim.x + threadIdx.x;
    if (i < NN) {
        int off = g_boff[i >> 10];
        int incl = g_rowoff[i + 1] + off;
        g_rowoff[i + 1] = incl;
        g_cursor[i] = incl - g_cnt[i];
    }
}

__global__ void scatter_kernel(const int* __restrict__ src, const int* __restrict__ dst, int n) {
    int i = blockIdx.x * blockDim.x + threadIdx.x;
    if (i < n) {
        int d = dst[i];
        int pos = atomicAdd(&g_cursor[d], 1);
        g_csr[pos] = src[i];
    }
}

// ---------------- aggregation: out[v] = sum_{e: dst=v} x[src[e]] ----------------
__global__ void agg_kernel(const float* __restrict__ x, float* __restrict__ out) {
    int v = blockIdx.x;
    int t = threadIdx.x;
    int beg = g_rowoff[v];
    int end = g_rowoff[v + 1];
    if (t < 75) {
        float4 acc = make_float4(0.f, 0.f, 0.f, 0.f);
        for (int e = beg; e < end; e++) {
            int s = g_csr[e];
            float4 val = ((const float4*)(x + (size_t)s * FD))[t];
            acc.x += val.x; acc.y += val.y; acc.z += val.z; acc.w += val.w;
        }
        ((float4*)(out + (size_t)v * FD))[t] = acc;
    }
}

// ---------------- TF32 tensor-core GEMM: C[M,300] = A[M,300] @ W[300,300]^T + bias ----------------
// Block tile 128x128, K-tile 32. 256 threads = 8 warps in 4(m) x 2(n); warp tile 32x64.
// mma.sync.m16n8k8.tf32: per warp 2 m-tiles x 8 n-tiles.
#define GBM 128
#define GBN 128
#define GBK 32
#define PADK 36

__device__ __forceinline__ unsigned f2tf32(float x) {
    unsigned u;
    asm("cvt.rna.tf32.f32 %0, %1;" : "=r"(u) : "f"(x));
    return u;
}

template <int RELU>
__global__ __launch_bounds__(256, 2) void gemm_tf32(const float* __restrict__ A,
                                                    const float* __restrict__ W,
                                                    const float* __restrict__ bias,
                                                    float* __restrict__ C, int M) {
    __shared__ unsigned As[GBM][PADK];
    __shared__ unsigned Ws[GBN][PADK];
    int tid  = threadIdx.x;
    int warp = tid >> 5, lane = tid & 31;
    int lq = lane & 3, lr = lane >> 2;       // lane%4, lane/4
    int wm = (warp >> 1) * 32;               // warp m offset (4 warps)
    int wn = (warp & 1) * 64;                // warp n offset (2 warps)
    int bm = blockIdx.x * GBM, bn = blockIdx.y * GBN;

    float acc[2][8][4];
    #pragma unroll
    for (int i = 0; i < 2; i++)
        #pragma unroll
        for (int j = 0; j < 8; j++)
            #pragma unroll
            for (int c = 0; c < 4; c++) acc[i][j][c] = 0.f;

    for (int k0 = 0; k0 < FD; k0 += GBK) {
        // ---- load A tile (128 x 32) ----
        #pragma unroll
        for (int i = 0; i < 4; i++) {
            int idx = tid + i * 256;
            int r = idx >> 3, kq = idx & 7;
            int gm = bm + r, k = k0 + kq * 4;
            float4 v = make_float4(0.f, 0.f, 0.f, 0.f);
            if (gm < M) {
                if (k + 3 < FD) v = *(const float4*)(A + (size_t)gm * FD + k);
                else {
                    const float* p = A + (size_t)gm * FD;
                    if (k + 0 < FD) v.x = p[k + 0];
                    if (k + 1 < FD) v.y = p[k + 1];
                    if (k + 2 < FD) v.z = p[k + 2];
                    if (k + 3 < FD) v.w = p[k + 3];
                }
            }
            As[r][kq * 4 + 0] = f2tf32(v.x);
            As[r][kq * 4 + 1] = f2tf32(v.y);
            As[r][kq * 4 + 2] = f2tf32(v.z);
            As[r][kq * 4 + 3] = f2tf32(v.w);
        }
        // ---- load W tile (128 x 32), row = output feature n ----
        #pragma unroll
        for (int i = 0; i < 4; i++) {
            int idx = tid + i * 256;
            int r = idx >> 3, kq = idx & 7;
            int gn = bn + r, k = k0 + kq * 4;
            float4 v = make_float4(0.f, 0.f, 0.f, 0.f);
            if (gn < FD) {
                if (k + 3 < FD) v = *(const float4*)(W + (size_t)gn * FD + k);
                else {
                    const float* p = W + (size_t)gn * FD;
                    if (k + 0 < FD) v.x = p[k + 0];
                    if (k + 1 < FD) v.y = p[k + 1];
                    if (k + 2 < FD) v.z = p[k + 2];
                    if (k + 3 < FD) v.w = p[k + 3];
                }
            }
            Ws[r][kq * 4 + 0] = f2tf32(v.x);
            Ws[r][kq * 4 + 1] = f2tf32(v.y);
            Ws[r][kq * 4 + 2] = f2tf32(v.z);
            Ws[r][kq * 4 + 3] = f2tf32(v.w);
        }
        __syncthreads();

        #pragma unroll
        for (int ks = 0; ks < 4; ks++) {
            int kk = ks * 8;
            unsigned a[2][4], b[8][2];
            #pragma unroll
            for (int i = 0; i < 2; i++) {
                int m = wm + i * 16 + lr;
                a[i][0] = As[m][kk + lq];
                a[i][1] = As[m + 8][kk + lq];
                a[i][2] = As[m][kk + lq + 4];
                a[i][3] = As[m + 8][kk + lq + 4];
            }
            #pragma unroll
            for (int j = 0; j < 8; j++) {
                int n = wn + j * 8 + lr;
                b[j][0] = Ws[n][kk + lq];
                b[j][1] = Ws[n][kk + lq + 4];
            }
            #pragma unroll
            for (int i = 0; i < 2; i++)
                #pragma unroll
                for (int j = 0; j < 8; j++)
                    asm volatile(
                        "mma.sync.aligned.m16n8k8.row.col.f32.tf32.tf32.f32 "
                        "{%0,%1,%2,%3},{%4,%5,%6,%7},{%8,%9},{%0,%1,%2,%3};"
                        : "+f"(acc[i][j][0]), "+f"(acc[i][j][1]),
                          "+f"(acc[i][j][2]), "+f"(acc[i][j][3])
                        : "r"(a[i][0]), "r"(a[i][1]), "r"(a[i][2]), "r"(a[i][3]),
                          "r"(b[j][0]), "r"(b[j][1]));
        }
        __syncthreads();
    }

    // ---- epilogue: bias (+relu), bounds-checked stores ----
    #pragma unroll
    for (int i = 0; i < 2; i++) {
        int m0 = bm + wm + i * 16 + lr;
        #pragma unroll
        for (int j = 0; j < 8; j++) {
            int n0 = bn + wn + j * 8 + lq * 2;
            #pragma unroll
            for (int h = 0; h < 2; h++) {   // h=0: rows m0 ; h=1: rows m0+8
                int gm = m0 + h * 8;
                if (gm >= M) continue;
                float v0 = acc[i][j][h * 2 + 0];
                float v1 = acc[i][j][h * 2 + 1];
                if (n0 < FD) {
                    float r0 = v0 + bias[n0];
                    if (RELU) r0 = fmaxf(r0, 0.f);
                    C[(size_t)gm * FD + n0] = r0;
                }
                if (n0 + 1 < FD) {
                    float r1 = v1 + bias[n0 + 1];
                    if (RELU) r1 = fmaxf(r1, 0.f);
                    C[(size_t)gm * FD + n0 + 1] = r1;
                }
            }
        }
    }
}

// ---------------- softmax over 300 (one block per row, 320 threads); bias already applied ----------------
__global__ __launch_bounds__(320) void softmax_kernel(const float* __restrict__ h,
                                                      float* __restrict__ out) {
    int v = blockIdx.x;
    int f = threadIdx.x;
    __shared__ float s_max[10];
    __shared__ float s_sum[10];
    __shared__ float s_m, s_s;

    float x = -1e30f;
    if (f < FD) x = __ldg(h + (size_t)v * FD + f);

    float m = x;
    #pragma unroll
    for (int off = 16; off; off >>= 1) m = fmaxf(m, __shfl_xor_sync(0xffffffffu, m, off));
    if ((f & 31) == 0) s_max[f >> 5] = m;
    __syncthreads();
    if (f < 32) {
        float t = (f < 10) ? s_max[f] : -1e30f;
        #pragma unroll
        for (int off = 16; off; off >>= 1) t = fmaxf(t, __shfl_xor_sync(0xffffffffu, t, off));
        if (f == 0) s_m = t;
    }
    __syncthreads();
    float mm = s_m;

    float e = (f < FD) ? __expf(x - mm) : 0.f;
    float s = e;
    #pragma unroll
    for (int off = 16; off; off >>= 1) s += __shfl_xor_sync(0xffffffffu, s, off);
    if ((f & 31) == 0) s_sum[f >> 5] = s;
    __syncthreads();
    if (f < 32) {
        float t = (f < 10) ? s_sum[f] : 0.f;
        #pragma unroll
        for (int off = 16; off; off >>= 1) t += __shfl_xor_sync(0xffffffffu, t, off);
        if (f == 0) s_s = t;
    }
    __syncthreads();
    if (f < FD) out[(size_t)v * FD + f] = e / s_s;
}

// ---------------- final layer: out = log_softmax(agg @ W4^T + b4), warp per node ----------------
__global__ void final_kernel(const float* __restrict__ agg, const float* __restrict__ W4,
                             const float* __restrict__ b4, float* __restrict__ out) {
    int warp = (blockIdx.x * blockDim.x + threadIdx.x) >> 5;
    int lane = threadIdx.x & 31;
    if (warp >= NN) return;
    const float* a = agg + (size_t)warp * FD;
    float s0 = 0.f, s1 = 0.f, s2 = 0.f;
    for (int k = lane; k < FD; k += 32) {
        float av = a[k];
        s0 += av * W4[k];
        s1 += av * W4[FD + k];
        s2 += av * W4[2 * FD + k];
    }
    #pragma unroll
    for (int off = 16; off; off >>= 1) {
        s0 += __shfl_down_sync(0xffffffffu, s0, off);
        s1 += __shfl_down_sync(0xffffffffu, s1, off);
        s2 += __shfl_down_sync(0xffffffffu, s2, off);
    }
    if (lane == 0) {
        s0 += b4[0]; s1 += b4[1]; s2 += b4[2];
        float m = fmaxf(s0, fmaxf(s1, s2));
        float lse = m + logf(expf(s0 - m) + expf(s1 - m) + expf(s2 - m));
        out[(size_t)warp * 3 + 0] = s0 - lse;
        out[(size_t)warp * 3 + 1] = s1 - lse;
        out[(size_t)warp * 3 + 2] = s2 - lse;
    }
}

// ---------------- launcher ----------------
extern "C" void kernel_launch(void* const* d_in, const int* in_sizes, int n_in,
                              void* d_out, int out_size) {
    const float* features = (const float*)d_in[0];
    const int*   src      = (const int*)d_in[1];
    const int*   dst      = (const int*)d_in[2];
    const float* W1 = (const float*)d_in[3];
    const float* b1 = (const float*)d_in[4];
    const float* W2 = (const float*)d_in[5];
    const float* b2 = (const float*)d_in[6];
    const float* W3 = (const float*)d_in[7];
    const float* b3 = (const float*)d_in[8];
    const float* W4 = (const float*)d_in[9];
    const float* b4 = (const float*)d_in[10];
    float* out = (float*)d_out;

    float *buf0, *buf1;
    int *cnt;
    cudaGetSymbolAddress((void**)&buf0, g_buf0);
    cudaGetSymbolAddress((void**)&buf1, g_buf1);
    cudaGetSymbolAddress((void**)&cnt,  g_cnt);

    const int E = NE;
    int eb = (E + 255) / 256;

    // CSR build (by destination)
    cudaMemsetAsync(cnt, 0, NN * sizeof(int));
    hist_kernel<<<eb, 256>>>(dst, E);
    scan1_kernel<<<(NN + 1023) / 1024, 1024>>>();
    scan2_kernel<<<1, 128>>>();
    scan3_kernel<<<(NN + 255) / 256, 256>>>();
    scatter_kernel<<<eb, 256>>>(src, dst, E);

    dim3 ggrid((NN + GBM - 1) / GBM, (FD + GBN - 1) / GBN);

    // Layer 1: agg(features)->buf0, gemm(+b1)->buf1, softmax->buf0
    agg_kernel<<<NN, 96>>>(features, buf0);
    gemm_tf32<0><<<ggrid, 256>>>(buf0, W1, b1, buf1, NN);
    softmax_kernel<<<NN, 320>>>(buf1, buf0);

    // Layer 2: agg(buf0)->buf1, gemm(+b2)->buf0, softmax->buf1
    agg_kernel<<<NN, 96>>>(buf0, buf1);
    gemm_tf32<0><<<ggrid, 256>>>(buf1, W2, b2, buf0, NN);
    softmax_kernel<<<NN, 320>>>(buf0, buf1);

    // Layer 3: agg(buf1)->buf0, gemm(+b3, relu)->buf1
    agg_kernel<<<NN, 96>>>(buf1, buf0);
    gemm_tf32<1><<<ggrid, 256>>>(buf0, W3, b3, buf1, NN);

    // Layer 4: agg(buf1)->buf0, fused small gemm + log_softmax -> out
    agg_kernel<<<NN, 96>>>(buf1, buf0);
    final_kernel<<<(NN * 32 + 255) / 256, 256>>>(buf0, W4, b4, out);
}

// round 4
// speedup vs baseline: 2.1710x; 1.4586x over previous
#include <cuda_runtime.h>
#include <math.h>
#include <stdint.h>

#define NN 100000
#define NE 800000
#define FD 300

// ---------------- scratch (no allocations allowed) ----------------
__device__ float g_buf0[(size_t)NN * FD];
__device__ float g_buf1[(size_t)NN * FD];
__device__ int   g_csr[NE];
__device__ int   g_rowoff[NN + 1];
__device__ int   g_cnt[NN];
__device__ int   g_cursor[NN];
__device__ int   g_bsum[128];
__device__ int   g_boff[128];

// ---------------- CSR build ----------------
__global__ void hist_kernel(const int* __restrict__ dst, int n) {
    int i = blockIdx.x * blockDim.x + threadIdx.x;
    if (i < n) atomicAdd(&g_cnt[dst[i]], 1);
}

__global__ void scan1_kernel() {
    __shared__ int sh[1024];
    int tid = threadIdx.x;
    int i = blockIdx.x * 1024 + tid;
    int v = (i < NN) ? g_cnt[i] : 0;
    sh[tid] = v;
    __syncthreads();
    #pragma unroll
    for (int off = 1; off < 1024; off <<= 1) {
        int t = (tid >= off) ? sh[tid - off] : 0;
        __syncthreads();
        sh[tid] += t;
        __syncthreads();
    }
    if (i < NN) g_rowoff[i + 1] = sh[tid];
    if (tid == 1023) g_bsum[blockIdx.x] = sh[1023];
}

__global__ void scan2_kernel() {
    __shared__ int sh[128];
    int tid = threadIdx.x;
    int v = (tid < 98) ? g_bsum[tid] : 0;
    sh[tid] = v;
    __syncthreads();
    #pragma unroll
    for (int off = 1; off < 128; off <<= 1) {
        int t = (tid >= off) ? sh[tid - off] : 0;
        __syncthreads();
        sh[tid] += t;
        __syncthreads();
    }
    g_boff[tid] = sh[tid] - v;
    if (tid == 0) g_rowoff[0] = 0;
}

__global__ void scan3_kernel() {
    int i = blockIdx.x * blockDim.x + threadIdx.x;
    if (i < NN) {
        int off = g_boff[i >> 10];
        int incl = g_rowoff[i + 1] + off;
        g_rowoff[i + 1] = incl;
        g_cursor[i] = incl - g_cnt[i];
    }
}

__global__ void scatter_kernel(const int* __restrict__ src, const int* __restrict__ dst, int n) {
    int i = blockIdx.x * blockDim.x + threadIdx.x;
    if (i < n) {
        int d = dst[i];
        int pos = atomicAdd(&g_cursor[d], 1);
        g_csr[pos] = src[i];
    }
}

// ---------------- aggregation: out[v] = sum_{e: dst=v} x[src[e]] ----------------
__global__ void agg_kernel(const float* __restrict__ x, float* __restrict__ out) {
    int v = blockIdx.x;
    int t = threadIdx.x;
    int beg = g_rowoff[v];
    int end = g_rowoff[v + 1];
    if (t < 75) {
        float4 acc = make_float4(0.f, 0.f, 0.f, 0.f);
        for (int e = beg; e < end; e++) {
            int s = g_csr[e];
            float4 val = ((const float4*)(x + (size_t)s * FD))[t];
            acc.x += val.x; acc.y += val.y; acc.z += val.z; acc.w += val.w;
        }
        ((float4*)(out + (size_t)v * FD))[t] = acc;
    }
}

// ---------------- TF32 tensor-core GEMM with cp.async double buffering ----------------
// C[M,300] = A[M,300] @ W[300,300]^T + bias (+relu)
// Block tile 128x128, K-tile 32, 2 stages. 256 threads = 8 warps (4m x 2n); warp tile 32x64.
#define GBM 128
#define GBN 128
#define GBK 32
#define PADK 36
#define NKT 10                      // ceil(300/32)
#define STAGE_U32 (2 * GBM * PADK)  // As + Ws per stage (u32 elements)
#define SMEM_BYTES (2 * STAGE_U32 * 4)

__device__ __forceinline__ void cpasync16(uint32_t saddr, const void* gptr, int srcsize) {
    asm volatile("cp.async.ca.shared.global [%0], [%1], 16, %2;\n"
                 :: "r"(saddr), "l"(gptr), "r"(srcsize));
}

template <int RELU>
__global__ __launch_bounds__(256, 2) void gemm_tf32(const float* __restrict__ A,
                                                    const float* __restrict__ W,
                                                    const float* __restrict__ bias,
                                                    float* __restrict__ C, int M) {
    extern __shared__ unsigned smem[];
    uint32_t smem_u32;
    asm("{ .reg .u64 t; cvta.to.shared.u64 t, %1; cvt.u32.u64 %0, t; }"
        : "=r"(smem_u32) : "l"(smem));

    int tid  = threadIdx.x;
    int warp = tid >> 5, lane = tid & 31;
    int lq = lane & 3, lr = lane >> 2;
    int wm = (warp >> 1) * 32;
    int wn = (warp & 1) * 64;
    int bm = blockIdx.x * GBM, bn = blockIdx.y * GBN;

    // ---- stage loader: issues 8 cp.async per thread (A then W tile) ----
    auto load_stage = [&](int s, int k0) {
        uint32_t sbase = smem_u32 + s * (STAGE_U32 * 4);
        #pragma unroll
        for (int i = 0; i < 4; i++) {
            int idx = tid + i * 256;
            int r = idx >> 3, kq = idx & 7;
            int gm = bm + r, k = k0 + kq * 4;
            const float* gp = A;
            int sz = 0;
            if (gm < M && k < FD) {
                gp = A + (size_t)gm * FD + k;
                int rem = (FD - k) * 4;
                sz = rem < 16 ? rem : 16;
            }
            cpasync16(sbase + (r * PADK + kq * 4) * 4, gp, sz);
        }
        uint32_t wbase = sbase + GBM * PADK * 4;
        #pragma unroll
        for (int i = 0; i < 4; i++) {
            int idx = tid + i * 256;
            int r = idx >> 3, kq = idx & 7;
            int gn = bn + r, k = k0 + kq * 4;
            const float* gp = W;
            int sz = 0;
            if (gn < FD && k < FD) {
                gp = W + (size_t)gn * FD + k;
                int rem = (FD - k) * 4;
                sz = rem < 16 ? rem : 16;
            }
            cpasync16(wbase + (r * PADK + kq * 4) * 4, gp, sz);
        }
    };

    float acc[2][8][4];
    #pragma unroll
    for (int i = 0; i < 2; i++)
        #pragma unroll
        for (int j = 0; j < 8; j++)
            #pragma unroll
            for (int c = 0; c < 4; c++) acc[i][j][c] = 0.f;

    load_stage(0, 0);
    asm volatile("cp.async.commit_group;");

    for (int t = 0; t < NKT; t++) {
        if (t + 1 < NKT) {
            load_stage((t + 1) & 1, (t + 1) * GBK);
            asm volatile("cp.async.commit_group;");
            asm volatile("cp.async.wait_group 1;");
        } else {
            asm volatile("cp.async.wait_group 0;");
        }
        __syncthreads();

        const unsigned* As = smem + (t & 1) * STAGE_U32;
        const unsigned* Ws = As + GBM * PADK;

        #pragma unroll
        for (int ks = 0; ks < 4; ks++) {
            int kk = ks * 8;
            unsigned a[2][4], b[8][2];
            #pragma unroll
            for (int i = 0; i < 2; i++) {
                int m = wm + i * 16 + lr;
                a[i][0] = As[m * PADK + kk + lq];
                a[i][1] = As[(m + 8) * PADK + kk + lq];
                a[i][2] = As[m * PADK + kk + lq + 4];
                a[i][3] = As[(m + 8) * PADK + kk + lq + 4];
            }
            #pragma unroll
            for (int j = 0; j < 8; j++) {
                int n = wn + j * 8 + lr;
                b[j][0] = Ws[n * PADK + kk + lq];
                b[j][1] = Ws[n * PADK + kk + lq + 4];
            }
            #pragma unroll
            for (int i = 0; i < 2; i++)
                #pragma unroll
                for (int j = 0; j < 8; j++)
                    asm volatile(
                        "mma.sync.aligned.m16n8k8.row.col.f32.tf32.tf32.f32 "
                        "{%0,%1,%2,%3},{%4,%5,%6,%7},{%8,%9},{%0,%1,%2,%3};"
                        : "+f"(acc[i][j][0]), "+f"(acc[i][j][1]),
                          "+f"(acc[i][j][2]), "+f"(acc[i][j][3])
                        : "r"(a[i][0]), "r"(a[i][1]), "r"(a[i][2]), "r"(a[i][3]),
                          "r"(b[j][0]), "r"(b[j][1]));
        }
        __syncthreads();
    }

    // ---- epilogue: bias (+relu) ----
    #pragma unroll
    for (int i = 0; i < 2; i++) {
        int m0 = bm + wm + i * 16 + lr;
        #pragma unroll
        for (int j = 0; j < 8; j++) {
            int n0 = bn + wn + j * 8 + lq * 2;
            #pragma unroll
            for (int h = 0; h < 2; h++) {
                int gm = m0 + h * 8;
                if (gm >= M) continue;
                if (n0 < FD) {
                    float r0 = acc[i][j][h * 2 + 0] + bias[n0];
                    if (RELU) r0 = fmaxf(r0, 0.f);
                    C[(size_t)gm * FD + n0] = r0;
                }
                if (n0 + 1 < FD) {
                    float r1 = acc[i][j][h * 2 + 1] + bias[n0 + 1];
                    if (RELU) r1 = fmaxf(r1, 0.f);
                    C[(size_t)gm * FD + n0 + 1] = r1;
                }
            }
        }
    }
}

// ---------------- softmax over 300 ----------------
__global__ __launch_bounds__(320) void softmax_kernel(const float* __restrict__ h,
                                                      float* __restrict__ out) {
    int v = blockIdx.x;
    int f = threadIdx.x;
    __shared__ float s_max[10];
    __shared__ float s_sum[10];
    __shared__ float s_m, s_s;

    float x = -1e30f;
    if (f < FD) x = __ldg(h + (size_t)v * FD + f);

    float m = x;
    #pragma unroll
    for (int off = 16; off; off >>= 1) m = fmaxf(m, __shfl_xor_sync(0xffffffffu, m, off));
    if ((f & 31) == 0) s_max[f >> 5] = m;
    __syncthreads();
    if (f < 32) {
        float t = (f < 10) ? s_max[f] : -1e30f;
        #pragma unroll
        for (int off = 16; off; off >>= 1) t = fmaxf(t, __shfl_xor_sync(0xffffffffu, t, off));
        if (f == 0) s_m = t;
    }
    __syncthreads();
    float mm = s_m;

    float e = (f < FD) ? __expf(x - mm) : 0.f;
    float s = e;
    #pragma unroll
    for (int off = 16; off; off >>= 1) s += __shfl_xor_sync(0xffffffffu, s, off);
    if ((f & 31) == 0) s_sum[f >> 5] = s;
    __syncthreads();
    if (f < 32) {
        float t = (f < 10) ? s_sum[f] : 0.f;
        #pragma unroll
        for (int off = 16; off; off >>= 1) t += __shfl_xor_sync(0xffffffffu, t, off);
        if (f == 0) s_s = t;
    }
    __syncthreads();
    if (f < FD) out[(size_t)v * FD + f] = e / s_s;
}

// ---------------- layer 4, step 1: per-node 3-dim projection y = x @ W4^T ----------------
__global__ void proj_kernel(const float* __restrict__ x, const float* __restrict__ W4,
                            float* __restrict__ y) {
    int warp = (blockIdx.x * blockDim.x + threadIdx.x) >> 5;
    int lane = threadIdx.x & 31;
    if (warp >= NN) return;
    const float* a = x + (size_t)warp * FD;
    float s0 = 0.f, s1 = 0.f, s2 = 0.f;
    for (int k = lane; k < FD; k += 32) {
        float av = a[k];
        s0 += av * W4[k];
        s1 += av * W4[FD + k];
        s2 += av * W4[2 * FD + k];
    }
    #pragma unroll
    for (int off = 16; off; off >>= 1) {
        s0 += __shfl_down_sync(0xffffffffu, s0, off);
        s1 += __shfl_down_sync(0xffffffffu, s1, off);
        s2 += __shfl_down_sync(0xffffffffu, s2, off);
    }
    if (lane == 0) {
        y[(size_t)warp * 3 + 0] = s0;
        y[(size_t)warp * 3 + 1] = s1;
        y[(size_t)warp * 3 + 2] = s2;
    }
}

// ---------------- layer 4, step 2: agg 3-wide + bias + log_softmax (thread per node) ----------------
__global__ void final3_kernel(const float* __restrict__ y, const float* __restrict__ b4,
                              float* __restrict__ out) {
    int v = blockIdx.x * blockDim.x + threadIdx.x;
    if (v >= NN) return;
    int beg = g_rowoff[v], end = g_rowoff[v + 1];
    float s0 = 0.f, s1 = 0.f, s2 = 0.f;
    for (int e = beg; e < end; e++) {
        int s = g_csr[e];
        s0 += y[(size_t)s * 3 + 0];
        s1 += y[(size_t)s * 3 + 1];
        s2 += y[(size_t)s * 3 + 2];
    }
    s0 += b4[0]; s1 += b4[1]; s2 += b4[2];
    float m = fmaxf(s0, fmaxf(s1, s2));
    float lse = m + logf(expf(s0 - m) + expf(s1 - m) + expf(s2 - m));
    out[(size_t)v * 3 + 0] = s0 - lse;
    out[(size_t)v * 3 + 1] = s1 - lse;
    out[(size_t)v * 3 + 2] = s2 - lse;
}

// ---------------- launcher ----------------
extern "C" void kernel_launch(void* const* d_in, const int* in_sizes, int n_in,
                              void* d_out, int out_size) {
    const float* features = (const float*)d_in[0];
    const int*   src      = (const int*)d_in[1];
    const int*   dst      = (const int*)d_in[2];
    const float* W1 = (const float*)d_in[3];
    const float* b1 = (const float*)d_in[4];
    const float* W2 = (const float*)d_in[5];
    const float* b2 = (const float*)d_in[6];
    const float* W3 = (const float*)d_in[7];
    const float* b3 = (const float*)d_in[8];
    const float* W4 = (const float*)d_in[9];
    const float* b4 = (const float*)d_in[10];
    float* out = (float*)d_out;

    float *buf0, *buf1;
    int *cnt;
    cudaGetSymbolAddress((void**)&buf0, g_buf0);
    cudaGetSymbolAddress((void**)&buf1, g_buf1);
    cudaGetSymbolAddress((void**)&cnt,  g_cnt);

    cudaFuncSetAttribute(gemm_tf32<0>, cudaFuncAttributeMaxDynamicSharedMemorySize, SMEM_BYTES);
    cudaFuncSetAttribute(gemm_tf32<1>, cudaFuncAttributeMaxDynamicSharedMemorySize, SMEM_BYTES);

    const int E = NE;
    int eb = (E + 255) / 256;

    // CSR build (by destination)
    cudaMemsetAsync(cnt, 0, NN * sizeof(int));
    hist_kernel<<<eb, 256>>>(dst, E);
    scan1_kernel<<<(NN + 1023) / 1024, 1024>>>();
    scan2_kernel<<<1, 128>>>();
    scan3_kernel<<<(NN + 255) / 256, 256>>>();
    scatter_kernel<<<eb, 256>>>(src, dst, E);

    dim3 ggrid((NN + GBM - 1) / GBM, (FD + GBN - 1) / GBN);

    // Layer 1
    agg_kernel<<<NN, 96>>>(features, buf0);
    gemm_tf32<0><<<ggrid, 256, SMEM_BYTES>>>(buf0, W1, b1, buf1, NN);
    softmax_kernel<<<NN, 320>>>(buf1, buf0);

    // Layer 2
    agg_kernel<<<NN, 96>>>(buf0, buf1);
    gemm_tf32<0><<<ggrid, 256, SMEM_BYTES>>>(buf1, W2, b2, buf0, NN);
    softmax_kernel<<<NN, 320>>>(buf0, buf1);

    // Layer 3 (relu fused in epilogue)
    agg_kernel<<<NN, 96>>>(buf1, buf0);
    gemm_tf32<1><<<ggrid, 256, SMEM_BYTES>>>(buf0, W3, b3, buf1, NN);

    // Layer 4: project to 3 dims FIRST (agg commutes with linear map), then 3-wide agg
    proj_kernel<<<(NN * 32 + 255) / 256, 256>>>(buf1, W4, buf0);
    final3_kernel<<<(NN + 255) / 256, 256>>>(buf0, b4, out);
}